// round 7
// baseline (speedup 1.0000x reference)
#include <cuda_runtime.h>
#include <math.h>

#define BATCH  64
#define LSUB   512
#define SWORDS 512
#define HID    768
#define NC     9
#define NWORDS (BATCH * SWORDS)
#define TROWS  (BATCH * LSUB)          // 32768 subword rows
#define YSTR   12                      // padded row stride of y
#define AGRID  444                     // 3 blocks/SM, one wave

typedef unsigned long long u64;

__device__ float g_y[TROWS * YSTR];    // per-subword logits (pre-bias), 1.5 MB
__device__ float g_ploss[BATCH];
__device__ int   g_pcnt[BATCH];
__device__ int   g_done;

__device__ __forceinline__ u64 fma2(u64 a, u64 b, u64 c) {
    u64 d; asm("fma.rn.f32x2 %0,%1,%2,%3;" : "=l"(d) : "l"(a), "l"(b), "l"(c)); return d;
}
__device__ __forceinline__ float upk_sum(u64 v) {
    float lo, hi; asm("mov.b64 {%0,%1},%2;" : "=f"(lo), "=f"(hi) : "l"(v)); return lo + hi;
}

// ---------------------------------------------------------------------------
// Pass A: per-subword GEMV. y[t, c] = x[t, :] . W[:, c] for ALL rows t
// (padding rows produce garbage, discarded in pass B). Fully regular:
// no predication, affine addresses, low regs -> 3 blocks/SM.
// ---------------------------------------------------------------------------
__global__ void __launch_bounds__(256, 3) gemv_kernel(
    const float* __restrict__ x, const float* __restrict__ W)
{
    __shared__ float Ws[NC * HID];     // Ws[c*HID + h]

    const int tid  = threadIdx.x;
    const int lane = tid & 31;
    const int warp = tid >> 5;

    // transpose W into shared: j = c*HID + h  (div by 768 = shift-mul)
    for (int j = tid; j < NC * HID; j += 256) {
        int c = j / HID;
        int h = j - c * HID;
        Ws[j] = W[h * NC + c];
    }
    if (blockIdx.x == 0 && tid == 0) g_done = 0;
    __syncthreads();

    const int gw = blockIdx.x * 8 + warp;
    const int nw = AGRID * 8;

#pragma unroll 1
    for (int p = gw; p < TROWS / 2; p += nw) {
        const ulonglong2* r0 = (const ulonglong2*)(x + (size_t)(2 * p) * HID);
        const ulonglong2* r1 = r0 + HID / 4;        // next row (192 chunks)

        u64 acc0[NC], acc1[NC];
#pragma unroll
        for (int c = 0; c < NC; c++) { acc0[c] = 0ull; acc1[c] = 0ull; }

#pragma unroll
        for (int g = 0; g < 6; g++) {
            int idx = g * 32 + lane;
            ulonglong2 a = r0[idx];
            ulonglong2 b = r1[idx];
            int hb = g * 128 + lane * 4;
#pragma unroll
            for (int c = 0; c < NC; c++) {
                ulonglong2 wc = *(const ulonglong2*)&Ws[c * HID + hb];
                acc0[c] = fma2(a.x, wc.x, acc0[c]);
                acc0[c] = fma2(a.y, wc.y, acc0[c]);
                acc1[c] = fma2(b.x, wc.x, acc1[c]);
                acc1[c] = fma2(b.y, wc.y, acc1[c]);
            }
        }

        float s0[NC], s1[NC];
#pragma unroll
        for (int c = 0; c < NC; c++) { s0[c] = upk_sum(acc0[c]); s1[c] = upk_sum(acc1[c]); }
#pragma unroll
        for (int c = 0; c < NC; c++) {
#pragma unroll
            for (int off = 16; off; off >>= 1) {
                s0[c] += __shfl_xor_sync(0xffffffffu, s0[c], off);
                s1[c] += __shfl_xor_sync(0xffffffffu, s1[c], off);
            }
        }

        if (lane == 0) {
            float* y0 = &g_y[(size_t)(2 * p) * YSTR];
#pragma unroll
            for (int c = 0; c < NC; c++) y0[c]        = s0[c];
#pragma unroll
            for (int c = 0; c < NC; c++) y0[YSTR + c] = s1[c];
        }
    }
}

// ---------------------------------------------------------------------------
// Pass B: 64 blocks (one per batch) x 256 threads. In-block scan of
// ids_lens, then each thread handles 2 words: segment-sum y, mean, +bias,
// softmax / argmax / NLL. Per-block loss partials; last block finalizes.
// ---------------------------------------------------------------------------
__global__ void __launch_bounds__(256) epi_kernel(
    const float* __restrict__ bias,
    const int*   __restrict__ ids_lens,
    const int*   __restrict__ label_ids,
    float*       __restrict__ out)       // out[0]=loss, out[1..]=pred
{
    __shared__ int   s_start[SWORDS];
    __shared__ int   s_wsum[8];
    __shared__ float s_lsum[8];
    __shared__ int   s_csum[8];
    __shared__ float sb[NC];

    const int b    = blockIdx.x;
    const int tid  = threadIdx.x;
    const int lane = tid & 31;
    const int warp = tid >> 5;

    if (tid < NC) sb[tid] = bias[tid];

    // scan this batch's lens (2 per thread)
    int2 lp = ((const int2*)(ids_lens + b * SWORDS))[tid];
    int sum2 = lp.x + lp.y;
    int inc = sum2;
#pragma unroll
    for (int off = 1; off < 32; off <<= 1) {
        int n = __shfl_up_sync(0xffffffffu, inc, off);
        if (lane >= off) inc += n;
    }
    int lane_ex = inc - sum2;
    if (lane == 31) s_wsum[warp] = inc;
    __syncthreads();
    int wbase = 0;
#pragma unroll
    for (int i = 0; i < 8; i++) if (i < warp) wbase += s_wsum[i];
    int ex0 = wbase + lane_ex;
    s_start[2 * tid]     = ex0;
    s_start[2 * tid + 1] = ex0 + lp.x;
    __syncthreads();

    float lloss = 0.0f;
    int   lcnt  = 0;

#pragma unroll
    for (int k = 0; k < 2; k++) {
        int wl  = 2 * tid + k;                  // word within batch
        int w   = b * SWORDS + wl;
        int len = (k == 0) ? lp.x : lp.y;
        int st  = s_start[wl];

        const float* yb = &g_y[((size_t)(b * LSUB) + st) * YSTR];
        float a[NC];
#pragma unroll
        for (int c = 0; c < NC; c++) a[c] = 0.0f;
        for (int r = 0; r < len; r++) {
#pragma unroll
            for (int c = 0; c < NC; c++) a[c] += yb[r * YSTR + c];
        }

        float inv = (len > 0) ? (1.0f / (float)len) : 0.0f;
        float lg[NC];
        float m = -1e30f; int am = 0;
#pragma unroll
        for (int c = 0; c < NC; c++) {
            lg[c] = fmaf(a[c], inv, sb[c]);
            if (lg[c] > m) { m = lg[c]; am = c; }
        }
        out[1 + w] = (float)am;
        if (len > 0) {
            float sum = 0.0f;
#pragma unroll
            for (int c = 0; c < NC; c++) sum += __expf(lg[c] - m);
            int lab = label_ids[w];
            lab = lab < 0 ? 0 : (lab > NC - 1 ? NC - 1 : lab);
            lloss += -(lg[lab] - m - __logf(sum));
            lcnt  += 1;
        }
    }

    // block reduce loss
#pragma unroll
    for (int off = 16; off; off >>= 1) {
        lloss += __shfl_xor_sync(0xffffffffu, lloss, off);
        lcnt  += __shfl_xor_sync(0xffffffffu, lcnt,  off);
    }
    if (lane == 0) { s_lsum[warp] = lloss; s_csum[warp] = lcnt; }
    __syncthreads();

    if (tid == 0) {
        float bl = 0.0f; int bc = 0;
#pragma unroll
        for (int i = 0; i < 8; i++) { bl += s_lsum[i]; bc += s_csum[i]; }
        g_ploss[b] = bl;
        g_pcnt[b]  = bc;
        __threadfence();
        int old = atomicAdd(&g_done, 1);
        if (old == BATCH - 1) {                 // last block finalizes
            float tl = 0.0f; int tc = 0;
            for (int i = 0; i < BATCH; i++) { tl += g_ploss[i]; tc += g_pcnt[i]; }
            out[0] = tl / fmaxf((float)tc, 1.0f);
        }
    }
}

extern "C" void kernel_launch(void* const* d_in, const int* in_sizes, int n_in,
                              void* d_out, int out_size) {
    const float* bert_out  = (const float*)d_in[0];
    const float* W         = (const float*)d_in[1];
    const float* b         = (const float*)d_in[2];
    const int*   ids_lens  = (const int*)d_in[4];
    const int*   label_ids = (const int*)d_in[5];
    float* out = (float*)d_out;

    gemv_kernel<<<AGRID, 256>>>(bert_out, W);
    epi_kernel<<<BATCH, 256>>>(b, ids_lens, label_ids, out);
}

// round 8
// speedup vs baseline: 3.1225x; 3.1225x over previous
#include <cuda_runtime.h>
#include <math.h>

#define BATCH  64
#define LSUB   512
#define SWORDS 512
#define HID    768
#define NC     9
#define NWORDS (BATCH * SWORDS)
#define MGRID  444          // 3 blocks/SM, one wave

typedef unsigned long long u64;

__device__ float g_Wt[NC * HID];      // transposed W: g_Wt[c*HID + h]
__device__ int   g_ls[NWORDS];        // packed (start<<2)|len
__device__ float g_loss;
__device__ int   g_cnt;
__device__ int   g_done;

__device__ __forceinline__ u64 fma2(u64 a, u64 b, u64 c) {
    u64 d; asm("fma.rn.f32x2 %0,%1,%2,%3;" : "=l"(d) : "l"(a), "l"(b), "l"(c)); return d;
}
__device__ __forceinline__ u64 add2(u64 a, u64 b) {
    u64 d; asm("add.rn.f32x2 %0,%1,%2;" : "=l"(d) : "l"(a), "l"(b)); return d;
}
__device__ __forceinline__ float upk_sum(u64 v) {
    float lo, hi; asm("mov.b64 {%0,%1},%2;" : "=f"(lo), "=f"(hi) : "l"(v)); return lo + hi;
}

// ---------------------------------------------------------------------------
// Setup: 64 blocks x 256 threads. Block b scans batch b's ids_lens, writes
// packed (start<<2)|len; transposes its 12-row W slice; block 0 resets accs.
// ---------------------------------------------------------------------------
__global__ void __launch_bounds__(256) setup_kernel(
    const int* __restrict__ ids_lens, const float* __restrict__ W)
{
    __shared__ int s_wsum[8];
    const int b = blockIdx.x, tid = threadIdx.x;
    const int lane = tid & 31, warp = tid >> 5;

    int2 lp = ((const int2*)(ids_lens + b * SWORDS))[tid];
    int sum2 = lp.x + lp.y;
    int inc = sum2;
#pragma unroll
    for (int off = 1; off < 32; off <<= 1) {
        int n = __shfl_up_sync(0xffffffffu, inc, off);
        if (lane >= off) inc += n;
    }
    int lane_ex = inc - sum2;
    if (lane == 31) s_wsum[warp] = inc;
    __syncthreads();
    int wbase = 0;
#pragma unroll
    for (int i = 0; i < 8; i++) if (i < warp) wbase += s_wsum[i];
    int ex0 = wbase + lane_ex;
    int base = b * SWORDS + 2 * tid;
    g_ls[base]     = (ex0 << 2) | lp.x;
    g_ls[base + 1] = ((ex0 + lp.x) << 2) | lp.y;

    if (tid < 12 * NC) {
        int h = b * 12 + tid / NC;
        int c = tid - (tid / NC) * NC;
        g_Wt[c * HID + h] = W[h * NC + c];
    }
    if (b == 0 && tid == 0) { g_loss = 0.0f; g_cnt = 0; g_done = 0; }
}

// ---------------------------------------------------------------------------
// Main: 444 blocks x 256 threads (3 blocks/SM, one wave). ONE word per warp
// per iteration: 9 u64 accumulators, 3 predicated row loads per group ->
// low register pressure, high occupancy. Last block finalizes loss.
// ---------------------------------------------------------------------------
__global__ void __launch_bounds__(256, 3) main_kernel(
    const float* __restrict__ x,        // [B, L, H]
    const float* __restrict__ bias,     // [C]
    const int*   __restrict__ label_ids,
    float*       __restrict__ out)      // out[0]=loss, out[1..]=pred
{
    __shared__ float Ws[NC * HID];      // Ws[c*HID + h]
    __shared__ float sb[NC];
    __shared__ float s_loss;
    __shared__ int   s_cnt;

    const int tid  = threadIdx.x;
    const int lane = tid & 31;
    const int warp = tid >> 5;

    {
        const float4* src = (const float4*)g_Wt;
        float4*       dst = (float4*)Ws;
        for (int i = tid; i < (NC * HID) / 4; i += 256) dst[i] = src[i];
    }
    if (tid < NC) sb[tid] = bias[tid];
    if (tid == 0) { s_loss = 0.0f; s_cnt = 0; }
    __syncthreads();

    const int gw = blockIdx.x * 8 + warp;
    const int nw = MGRID * 8;

    float lloss = 0.0f;
    int   lcnt  = 0;

    const ulonglong2 z2 = make_ulonglong2(0ull, 0ull);
    const int RS = HID / 4;             // row stride in 16B chunks = 192

#pragma unroll 1
    for (int w = gw; w < NWORDS; w += nw) {
        int batch = w >> 9;
        int ls  = g_ls[w];
        int len = ls & 3;
        int st  = ls >> 2;

        const ulonglong2* base = (const ulonglong2*)(x + ((size_t)(batch * LSUB + st)) * HID);

        u64 acc[NC];
#pragma unroll
        for (int c = 0; c < NC; c++) acc[c] = 0ull;

#pragma unroll
        for (int g = 0; g < 6; g++) {
            int idx = g * 32 + lane;
            ulonglong2 a0 = (len > 0) ? base[idx]          : z2;
            ulonglong2 a1 = (len > 1) ? base[idx + RS]     : z2;
            ulonglong2 a2 = (len > 2) ? base[idx + 2 * RS] : z2;

            u64 vl = add2(a0.x, add2(a1.x, a2.x));
            u64 vh = add2(a0.y, add2(a1.y, a2.y));

            int hb = g * 128 + lane * 4;
#pragma unroll
            for (int c = 0; c < NC; c++) {
                ulonglong2 wc = *(const ulonglong2*)&Ws[c * HID + hb];
                acc[c] = fma2(vl, wc.x, acc[c]);
                acc[c] = fma2(vh, wc.y, acc[c]);
            }
        }

        float r[NC];
#pragma unroll
        for (int c = 0; c < NC; c++) r[c] = upk_sum(acc[c]);
#pragma unroll
        for (int c = 0; c < NC; c++) {
#pragma unroll
            for (int off = 16; off; off >>= 1)
                r[c] += __shfl_xor_sync(0xffffffffu, r[c], off);
        }

        if (lane == 0) {
            float inv = (len > 0) ? (1.0f / (float)len) : 0.0f;
            float lg[NC];
            float m = -1e30f; int am = 0;
#pragma unroll
            for (int c = 0; c < NC; c++) {
                lg[c] = fmaf(r[c], inv, sb[c]);
                if (lg[c] > m) { m = lg[c]; am = c; }
            }
            out[1 + w] = (float)am;
            if (len > 0) {
                float sum = 0.0f;
#pragma unroll
                for (int c = 0; c < NC; c++) sum += __expf(lg[c] - m);
                int lab = label_ids[w];
                lab = lab < 0 ? 0 : (lab > NC - 1 ? NC - 1 : lab);
                lloss += -(lg[lab] - m - __logf(sum));
                lcnt  += 1;
            }
        }
    }

    if (lane == 0 && lcnt > 0) {
        atomicAdd(&s_loss, lloss);
        atomicAdd(&s_cnt, lcnt);
    }
    __syncthreads();

    if (tid == 0) {
        if (s_cnt > 0) {
            atomicAdd(&g_loss, s_loss);
            atomicAdd(&g_cnt, s_cnt);
        }
        __threadfence();
        int old = atomicAdd(&g_done, 1);
        if (old == MGRID - 1) {
            float lv = atomicAdd(&g_loss, 0.0f);
            int   cv = atomicAdd(&g_cnt, 0);
            out[0] = lv / fmaxf((float)cv, 1.0f);
        }
    }
}

extern "C" void kernel_launch(void* const* d_in, const int* in_sizes, int n_in,
                              void* d_out, int out_size) {
    const float* bert_out  = (const float*)d_in[0];
    const float* W         = (const float*)d_in[1];
    const float* b         = (const float*)d_in[2];
    const int*   ids_lens  = (const int*)d_in[4];
    const int*   label_ids = (const int*)d_in[5];
    float* out = (float*)d_out;

    setup_kernel<<<BATCH, 256>>>(ids_lens, W);
    main_kernel<<<MGRID, 256>>>(bert_out, b, label_ids, out);
}

// round 9
// speedup vs baseline: 4.9425x; 1.5828x over previous
#include <cuda_runtime.h>
#include <math.h>

#define BATCH  64
#define LSUB   512
#define SWORDS 512
#define HID    768
#define NC     9
#define NWORDS (BATCH * SWORDS)
#define MGRID  296          // 2 blocks/SM, one wave

typedef unsigned long long u64;

__device__ float g_Wt[NC * HID];      // transposed W: g_Wt[c*HID + h]
__device__ int   g_ls[NWORDS];        // packed (start<<2)|len
__device__ int   g_nv[BATCH];         // valid (len>0) words per batch (prefix)
__device__ float g_loss;
__device__ int   g_cnt;
__device__ int   g_done;

__device__ __forceinline__ u64 fma2(u64 a, u64 b, u64 c) {
    u64 d; asm("fma.rn.f32x2 %0,%1,%2,%3;" : "=l"(d) : "l"(a), "l"(b), "l"(c)); return d;
}
__device__ __forceinline__ u64 add2(u64 a, u64 b) {
    u64 d; asm("add.rn.f32x2 %0,%1,%2;" : "=l"(d) : "l"(a), "l"(b)); return d;
}
__device__ __forceinline__ float upk_sum(u64 v) {
    float lo, hi; asm("mov.b64 {%0,%1},%2;" : "=f"(lo), "=f"(hi) : "l"(v)); return lo + hi;
}

// ---------------------------------------------------------------------------
// Setup: 64 blocks x 256 threads. Block b: scan ids_lens -> g_ls (packed),
// count valid words -> g_nv[b], transpose W slice, fill default preds
// (= argmax(bias), reference gives invalid words logits = bias).
// ---------------------------------------------------------------------------
__global__ void __launch_bounds__(256) setup_kernel(
    const int* __restrict__ ids_lens, const float* __restrict__ W,
    const float* __restrict__ bias, float* __restrict__ out)
{
    __shared__ int s_wsum[8];
    __shared__ int s_vcnt[8];
    const int b = blockIdx.x, tid = threadIdx.x;
    const int lane = tid & 31, warp = tid >> 5;

    int2 lp = ((const int2*)(ids_lens + b * SWORDS))[tid];
    int sum2 = lp.x + lp.y;
    int inc = sum2;
#pragma unroll
    for (int off = 1; off < 32; off <<= 1) {
        int n = __shfl_up_sync(0xffffffffu, inc, off);
        if (lane >= off) inc += n;
    }
    int lane_ex = inc - sum2;
    // valid-word count (len>0)
    int vc = (lp.x > 0) + (lp.y > 0);
#pragma unroll
    for (int off = 16; off; off >>= 1) vc += __shfl_xor_sync(0xffffffffu, vc, off);
    if (lane == 31) s_wsum[warp] = inc;
    if (lane == 0)  s_vcnt[warp] = vc;
    __syncthreads();
    int wbase = 0;
#pragma unroll
    for (int i = 0; i < 8; i++) if (i < warp) wbase += s_wsum[i];
    int ex0 = wbase + lane_ex;
    int base = b * SWORDS + 2 * tid;
    g_ls[base]     = (ex0 << 2) | lp.x;
    g_ls[base + 1] = ((ex0 + lp.x) << 2) | lp.y;

    // default preds = argmax(bias) (first-max, matching jnp.argmax)
    {
        float m = -1e30f; int am = 0;
#pragma unroll
        for (int c = 0; c < NC; c++) {
            float v = bias[c];
            if (v > m) { m = v; am = c; }
        }
        float amf = (float)am;
        out[1 + base]     = amf;
        out[1 + base + 1] = amf;
    }

    if (tid < 12 * NC) {
        int h = b * 12 + tid / NC;
        int c = tid - (tid / NC) * NC;
        g_Wt[c * HID + h] = W[h * NC + c];
    }
    if (tid == 0) {
        int tot = 0;
#pragma unroll
        for (int i = 0; i < 8; i++) tot += s_vcnt[i];
        g_nv[b] = tot;
        if (b == 0) { g_loss = 0.0f; g_cnt = 0; g_done = 0; }
    }
}

// ---------------------------------------------------------------------------
// Main: 296 blocks x 256 threads, 2 blocks/SM. Warps grid-stride over pairs
// of VALID words only (~16K valid of 32K). Valid index -> batch via 6-step
// binary search over the 64-entry offset table in shared.
// ---------------------------------------------------------------------------
__global__ void __launch_bounds__(256, 2) main_kernel(
    const float* __restrict__ x,        // [B, L, H]
    const float* __restrict__ bias,     // [C]
    const int*   __restrict__ label_ids,
    float*       __restrict__ out)      // out[0]=loss, out[1..]=pred
{
    __shared__ float Ws[NC * HID];      // Ws[c*HID + h]
    __shared__ int   s_off[BATCH + 1];  // valid-word offsets per batch
    __shared__ float sb[NC];
    __shared__ float s_loss;
    __shared__ int   s_cnt;

    const int tid  = threadIdx.x;
    const int lane = tid & 31;
    const int warp = tid >> 5;

    {
        const float4* src = (const float4*)g_Wt;
        float4*       dst = (float4*)Ws;
        for (int i = tid; i < (NC * HID) / 4; i += 256) dst[i] = src[i];
    }
    if (tid < NC) sb[tid] = bias[tid];
    if (tid == 0) { s_loss = 0.0f; s_cnt = 0; s_off[0] = 0; }
    // warp 0 builds the offset prefix (2 batches per lane)
    if (warp == 0) {
        int a  = g_nv[2 * lane];
        int b2 = g_nv[2 * lane + 1];
        int s  = a + b2;
        int inc = s;
#pragma unroll
        for (int off = 1; off < 32; off <<= 1) {
            int n = __shfl_up_sync(0xffffffffu, inc, off);
            if (lane >= off) inc += n;
        }
        int ex = inc - s;
        s_off[2 * lane + 1] = ex + a;
        s_off[2 * lane + 2] = inc;
    }
    __syncthreads();

    const int total  = s_off[BATCH];        // total valid words
    const int npairs = (total + 1) >> 1;
    const int gw = blockIdx.x * 8 + warp;
    const int nw = MGRID * 8;

    float lloss = 0.0f;
    int   lcnt  = 0;

    const ulonglong2 z2 = make_ulonglong2(0ull, 0ull);
    const int RS = HID / 4;                 // row stride in 16B chunks = 192

#pragma unroll 1
    for (int p = gw; p < npairs; p += nw) {
        int j0 = 2 * p, j1 = 2 * p + 1;
        bool act1 = (j1 < total);

        // valid index -> (batch, word) via binary search in s_off
        int lo = 0, hi = BATCH;
#pragma unroll
        for (int s = 0; s < 6; s++) { int mid = (lo + hi) >> 1; if (s_off[mid] <= j0) lo = mid; else hi = mid; }
        int b0 = lo;
        int w0 = b0 * SWORDS + (j0 - s_off[b0]);

        lo = b0; hi = BATCH;                // j1 >= j0 -> batch >= b0
#pragma unroll
        for (int s = 0; s < 6; s++) { int mid = (lo + hi) >> 1; if (s_off[mid] <= j1) lo = mid; else hi = mid; }
        int b1 = lo;
        int w1 = b1 * SWORDS + (j1 - s_off[b1]);

        int ls0 = g_ls[w0];
        int ls1 = act1 ? g_ls[w1] : 0;
        int len0 = ls0 & 3, len1 = ls1 & 3;
        int st0  = ls0 >> 2, st1 = ls1 >> 2;

        const ulonglong2* base0 = (const ulonglong2*)(x + ((size_t)(b0 * LSUB + st0)) * HID);
        const ulonglong2* base1 = (const ulonglong2*)(x + ((size_t)(b1 * LSUB + st1)) * HID);

        u64 acc0[NC], acc1[NC];
#pragma unroll
        for (int c = 0; c < NC; c++) { acc0[c] = 0ull; acc1[c] = 0ull; }

#pragma unroll
        for (int g = 0; g < 6; g++) {
            int idx = g * 32 + lane;
            ulonglong2 a0 = (len0 > 0) ? base0[idx]          : z2;
            ulonglong2 a1 = (len0 > 1) ? base0[idx + RS]     : z2;
            ulonglong2 a2 = (len0 > 2) ? base0[idx + 2 * RS] : z2;
            ulonglong2 c0 = (len1 > 0) ? base1[idx]          : z2;
            ulonglong2 c1 = (len1 > 1) ? base1[idx + RS]     : z2;
            ulonglong2 c2 = (len1 > 2) ? base1[idx + 2 * RS] : z2;

            u64 v0l = add2(a0.x, add2(a1.x, a2.x));
            u64 v0h = add2(a0.y, add2(a1.y, a2.y));
            u64 v1l = add2(c0.x, add2(c1.x, c2.x));
            u64 v1h = add2(c0.y, add2(c1.y, c2.y));

            int hb = g * 128 + lane * 4;
#pragma unroll
            for (int c = 0; c < NC; c++) {
                ulonglong2 wc = *(const ulonglong2*)&Ws[c * HID + hb];
                acc0[c] = fma2(v0l, wc.x, acc0[c]);
                acc0[c] = fma2(v0h, wc.y, acc0[c]);
                acc1[c] = fma2(v1l, wc.x, acc1[c]);
                acc1[c] = fma2(v1h, wc.y, acc1[c]);
            }
        }

        float r0[NC], r1[NC];
#pragma unroll
        for (int c = 0; c < NC; c++) { r0[c] = upk_sum(acc0[c]); r1[c] = upk_sum(acc1[c]); }
#pragma unroll
        for (int c = 0; c < NC; c++) {
#pragma unroll
            for (int off = 16; off; off >>= 1) {
                r0[c] += __shfl_xor_sync(0xffffffffu, r0[c], off);
                r1[c] += __shfl_xor_sync(0xffffffffu, r1[c], off);
            }
        }

        if (lane == 0) {
#pragma unroll
            for (int which = 0; which < 2; which++) {
                if (which == 1 && !act1) break;
                int    w   = which ? w1 : w0;
                int    len = which ? len1 : len0;
                float* a   = which ? r1 : r0;

                float inv = 1.0f / (float)len;     // valid words: len >= 1
                float lg[NC];
                float m = -1e30f; int am = 0;
#pragma unroll
                for (int c = 0; c < NC; c++) {
                    lg[c] = fmaf(a[c], inv, sb[c]);
                    if (lg[c] > m) { m = lg[c]; am = c; }
                }
                out[1 + w] = (float)am;
                float sum = 0.0f;
#pragma unroll
                for (int c = 0; c < NC; c++) sum += __expf(lg[c] - m);
                int lab = label_ids[w];
                lab = lab < 0 ? 0 : (lab > NC - 1 ? NC - 1 : lab);
                lloss += -(lg[lab] - m - __logf(sum));
                lcnt  += 1;
            }
        }
    }

    if (lane == 0 && lcnt > 0) {
        atomicAdd(&s_loss, lloss);
        atomicAdd(&s_cnt, lcnt);
    }
    __syncthreads();

    if (tid == 0) {
        if (s_cnt > 0) {
            atomicAdd(&g_loss, s_loss);
            atomicAdd(&g_cnt, s_cnt);
        }
        __threadfence();
        int old = atomicAdd(&g_done, 1);
        if (old == MGRID - 1) {
            float lv = atomicAdd(&g_loss, 0.0f);
            int   cv = atomicAdd(&g_cnt, 0);
            out[0] = lv / fmaxf((float)cv, 1.0f);
        }
    }
}

extern "C" void kernel_launch(void* const* d_in, const int* in_sizes, int n_in,
                              void* d_out, int out_size) {
    const float* bert_out  = (const float*)d_in[0];
    const float* W         = (const float*)d_in[1];
    const float* b         = (const float*)d_in[2];
    const int*   ids_lens  = (const int*)d_in[4];
    const int*   label_ids = (const int*)d_in[5];
    float* out = (float*)d_out;

    setup_kernel<<<BATCH, 256>>>(ids_lens, W, b, out);
    main_kernel<<<MGRID, 256>>>(bert_out, b, label_ids, out);
}